// round 12
// baseline (speedup 1.0000x reference)
#include <cuda_runtime.h>
#include <cuda_bf16.h>
#include <math.h>

// ---------------- problem constants ----------------
#define BGR   32
#define NPG   256
#define NNC   8192
#define EC    65536
#define FD    128
#define EDIMC 16
#define ESMC  1280
#define HC    4
#define DHC   128
#define HDC   512
#define ATTN_SCALE 0.08838834764831845f  // 1/sqrt(128)
#define CHUNK 64

// packed fp32 helpers (Blackwell f32x2 pipe — 2 FMAs per issue)
#define FFMA2(d,a,b) asm("fma.rn.f32x2 %0, %1, %2, %0;" : "+l"(d) : "l"(a), "l"(b))
#define DUP2(d,s)    asm("mov.b64 %0, {%1, %1};" : "=l"(d) : "f"(s))

// ---------------- device scratch ----------------
__device__ float g_q [NNC*HDC];
__device__ float g_k [NNC*HDC];
__device__ float g_v [NNC*HDC];
__device__ float g_xr[NNC*HDC];
__device__ float g_h2[NNC*HDC];
__device__ float g_P [NNC*64];
__device__ float g_T [NNC*64];
__device__ float g_hA[NNC*FD];
__device__ float g_hB[NNC*FD];
__device__ int   g_deg[NNC];
__device__ int   g_row[NNC+1];
__device__ int   g_csr[EC];
__device__ int   g_nmask[NNC];
__device__ int   g_perm[NNC];
__device__ float g_s[NNC];
__device__ float g_rep[BGR*256];
__device__ float g_gin[BGR*1536];
__device__ float g_m1[BGR*512];
__device__ float g_m2[BGR*256];
// precomputed weight folds
__device__ float g_Wqe [5*128*512];   // padded: cols 0..63 real, rest 0
__device__ float g_bPe [5*128];
__device__ float g_Wcomb[5*576*128];  // rows 0..511 = Wt, rows 512.. = We@Wt
__device__ float g_WbWe [5*64];

// ---------------- precompute kernels ----------------
__global__ void prec_wqe(const float* __restrict__ Wq, const float* __restrict__ We,
                         float* __restrict__ Wqe)
{
    int idx = blockIdx.x*blockDim.x + threadIdx.x;
    if (idx >= 5*128*512) return;
    int li = idx / 65536;
    int r  = idx % 65536;
    int kk = r / 512, c = r % 512;
    float val = 0.f;
    if (c < 64){
        int h = c >> 4, j = c & 15;
        const float* a = Wq + (size_t)li*128*512 + (size_t)kk*512 + h*128;
        const float* b = We + (size_t)li*16*512 + (size_t)j*512 + h*128;
        for (int d=0; d<128; ++d) val += a[d]*b[d];
    }
    Wqe[idx] = val;
}
__global__ void prec_bpe(const float* __restrict__ bq, const float* __restrict__ We,
                         float* __restrict__ bPe)
{
    int idx = blockIdx.x*blockDim.x + threadIdx.x;
    if (idx >= 5*128) return;
    int li = idx / 128, c = idx % 128;
    float val = 0.f;
    if (c < 64){
        int h = c >> 4, j = c & 15;
        const float* a = bq + (size_t)li*512 + h*128;
        const float* b = We + (size_t)li*16*512 + (size_t)j*512 + h*128;
        for (int d=0; d<128; ++d) val += a[d]*b[d];
    }
    bPe[idx] = val;
}
__global__ void prec_wcomb(const float* __restrict__ Wt, const float* __restrict__ We,
                           float* __restrict__ Wc)
{
    int idx = blockIdx.x*blockDim.x + threadIdx.x;
    if (idx >= 5*576*128) return;
    int li = idx / (576*128);
    int r  = idx % (576*128);
    int rowk = r / 128, f = r % 128;
    float val;
    if (rowk < 512){
        val = Wt[(size_t)li*512*128 + (size_t)rowk*128 + f];
    } else {
        int c = rowk - 512;
        int h = c >> 4, j = c & 15;
        const float* we = We + (size_t)li*16*512 + (size_t)j*512 + h*128;
        const float* wt = Wt + (size_t)li*512*128 + (size_t)(h*128)*128 + f;
        float s = 0.f;
        for (int d=0; d<128; ++d) s += we[d]*wt[(size_t)d*128];
        val = s;
    }
    Wc[idx] = val;
}
__global__ void prec_wbwe(const float* __restrict__ We, const float* __restrict__ Wbeta,
                          float* __restrict__ WbWe)
{
    int idx = blockIdx.x*blockDim.x + threadIdx.x;
    if (idx >= 5*64) return;
    int li = idx / 64, c = idx % 64;
    int h = c >> 4, j = c & 15;
    const float* we = We + (size_t)li*16*512 + (size_t)j*512 + h*128;
    const float* w1 = Wbeta + (size_t)li*1536 + h*128;
    const float* w3 = Wbeta + (size_t)li*1536 + 1024 + h*128;
    float s = 0.f;
    for (int d=0; d<128; ++d) s += we[d]*(w1[d]+w3[d]);
    WbWe[idx] = s;
}

// ---------------- CSR build ----------------
__global__ void k_init(int* deg, int* nmask, int initMask){
    int i = blockIdx.x*blockDim.x + threadIdx.x;
    if (i < NNC){ deg[i]=0; if (initMask) nmask[i]=1; }
}
__global__ void k_count(const int* __restrict__ src, const int* __restrict__ dst,
                        const int* __restrict__ nmask, int useMask, int* deg){
    int e = blockIdx.x*blockDim.x + threadIdx.x;
    if (e < EC){
        int d = dst[e];
        if (!useMask || (nmask[d] && nmask[src[e]])) atomicAdd(&deg[d], 1);
    }
}
__global__ void k_scan(int* deg, int* row, int* cur){
    __shared__ int part[256];
    int t = threadIdx.x;
    int base = t*32;
    int loc[32];
    int s = 0;
    for (int i=0;i<32;i++){ loc[i] = deg[base+i]; s += loc[i]; }
    part[t] = s;
    __syncthreads();
    if (t == 0){
        int run = 0;
        for (int i=0;i<256;i++){ int tmp = part[i]; part[i] = run; run += tmp; }
    }
    __syncthreads();
    int run = part[t];
    for (int i=0;i<32;i++){ row[base+i] = run; cur[base+i] = run; run += loc[i]; }
    if (t == 255) row[NNC] = run;
}
__global__ void k_fill(const int* __restrict__ src, const int* __restrict__ dst,
                       const int* __restrict__ nmask, int useMask,
                       int* cur, int* csr){
    int e = blockIdx.x*blockDim.x + threadIdx.x;
    if (e < EC){
        int d = dst[e];
        if (!useMask || (nmask[d] && nmask[src[e]])){
            int pos = atomicAdd(&cur[d], 1);
            csr[pos] = e;
        }
    }
}

// ---------------- GEMM: fused Q/K/V/skip/P (5 segments), f32x2, double-buffered ----------------
__global__ void __launch_bounds__(256, 2) gemm_qkvs(
    const float* __restrict__ A, const int* __restrict__ perm,
    const float* __restrict__ W0,const float* __restrict__ W1,
    const float* __restrict__ W2,const float* __restrict__ W3,
    const float* __restrict__ Wp,
    const float* __restrict__ b0,const float* __restrict__ b1,
    const float* __restrict__ b2,const float* __restrict__ b3,
    const float* __restrict__ bP,
    float* __restrict__ C0,float* __restrict__ C1,
    float* __restrict__ C2,float* __restrict__ C3,
    float* __restrict__ CP)
{
    const int K = 128, NW = 512;
    int y   = blockIdx.y;
    int seg = y >> 2;                 // 0..4 (y==16 -> seg 4)
    int n0  = (y & 3) << 7;
    const float* W; const float* bias;
    if      (seg==0){ W=W0; bias=b0; }
    else if (seg==1){ W=W1; bias=b1; }
    else if (seg==2){ W=W2; bias=b2; }
    else if (seg==3){ W=W3; bias=b3; }
    else            { W=Wp; bias=bP; }
    int m0 = blockIdx.x << 7;

    __shared__ float As[2][16][128];
    __shared__ float Bs[2][16][128];
    int tid = threadIdx.x;
    int tr = (tid >> 4) << 3;
    int tc = (tid & 15) << 3;
    unsigned long long acc[8][4];
#pragma unroll
    for (int i=0;i<8;i++)
#pragma unroll
        for (int j=0;j<4;j++) acc[i][j]=0ull;

    int ar = tid >> 1, ac = (tid & 1) << 3;
    int wr = tid >> 4, wc = (tid & 15) << 3;
    int nodeA = perm ? perm[m0 + ar] : (m0 + ar);
    const float* Aptr = A + (size_t)nodeA*K + ac;
    const float* Wptr = W + (size_t)wr*NW + n0+wc;

    float4 av0 = *(const float4*)(Aptr);
    float4 av1 = *(const float4*)(Aptr+4);
    float4 bv0 = *(const float4*)(Wptr);
    float4 bv1 = *(const float4*)(Wptr+4);
    // store stage 0
    As[0][ac+0][ar]=av0.x; As[0][ac+1][ar]=av0.y; As[0][ac+2][ar]=av0.z; As[0][ac+3][ar]=av0.w;
    As[0][ac+4][ar]=av1.x; As[0][ac+5][ar]=av1.y; As[0][ac+6][ar]=av1.z; As[0][ac+7][ar]=av1.w;
    *(float4*)&Bs[0][wr][wc]   = bv0;
    *(float4*)&Bs[0][wr][wc+4] = bv1;

    for (int c=0; c<8; ++c){
        int st = c & 1;
        __syncthreads();
        if (c < 7){
            int k0 = (c+1)*16;
            av0 = *(const float4*)(Aptr + k0);
            av1 = *(const float4*)(Aptr + k0+4);
            bv0 = *(const float4*)(Wptr + (size_t)k0*NW);
            bv1 = *(const float4*)(Wptr + (size_t)k0*NW + 4);
        }
#pragma unroll
        for (int kk=0; kk<16; ++kk){
            float4 ra0 = *(const float4*)&As[st][kk][tr];
            float4 ra1 = *(const float4*)&As[st][kk][tr+4];
            ulonglong2 rbA = *(const ulonglong2*)&Bs[st][kk][tc];
            ulonglong2 rbB = *(const ulonglong2*)&Bs[st][kk][tc+4];
            unsigned long long rp[8];
            DUP2(rp[0], ra0.x); DUP2(rp[1], ra0.y); DUP2(rp[2], ra0.z); DUP2(rp[3], ra0.w);
            DUP2(rp[4], ra1.x); DUP2(rp[5], ra1.y); DUP2(rp[6], ra1.z); DUP2(rp[7], ra1.w);
#pragma unroll
            for (int i=0;i<8;i++){
                FFMA2(acc[i][0], rp[i], rbA.x);
                FFMA2(acc[i][1], rp[i], rbA.y);
                FFMA2(acc[i][2], rp[i], rbB.x);
                FFMA2(acc[i][3], rp[i], rbB.y);
            }
        }
        if (c < 7){
            int ns = st ^ 1;
            As[ns][ac+0][ar]=av0.x; As[ns][ac+1][ar]=av0.y; As[ns][ac+2][ar]=av0.z; As[ns][ac+3][ar]=av0.w;
            As[ns][ac+4][ar]=av1.x; As[ns][ac+5][ar]=av1.y; As[ns][ac+6][ar]=av1.z; As[ns][ac+7][ar]=av1.w;
            *(float4*)&Bs[ns][wr][wc]   = bv0;
            *(float4*)&Bs[ns][wr][wc+4] = bv1;
        }
    }
    if (seg < 4){
        float* C = seg==0?C0: seg==1?C1: seg==2?C2:C3;
#pragma unroll
        for (int i=0;i<8;i++){
            int nodeC = perm ? perm[m0+tr+i] : (m0+tr+i);
            float* Crow = C + (size_t)nodeC*NW + n0+tc;
#pragma unroll
            for (int j=0;j<4;j++){
                float2 p = *(float2*)&acc[i][j];
                Crow[2*j+0] = p.x + bias[n0+tc+2*j+0];
                Crow[2*j+1] = p.y + bias[n0+tc+2*j+1];
            }
        }
    } else if (tc < 64){
#pragma unroll
        for (int i=0;i<8;i++){
            int nodeC = perm ? perm[m0+tr+i] : (m0+tr+i);
            float* Crow = CP + (size_t)nodeC*64 + tc;
#pragma unroll
            for (int j=0;j<4;j++){
                float2 p = *(float2*)&acc[i][j];
                Crow[2*j+0] = p.x + bias[tc+2*j+0];
                Crow[2*j+1] = p.y + bias[tc+2*j+1];
            }
        }
    }
}

// ---------------- GEMM 64x64, K=576 (h2core | T), ReLU+BN epilogue ----------------
__global__ void __launch_bounds__(256) gemm64(
    const float* __restrict__ h2, const float* __restrict__ T,
    const int* __restrict__ perm,
    const float* __restrict__ Wc, const float* __restrict__ bias,
    float* __restrict__ C,
    const float* __restrict__ gamma, const float* __restrict__ beta,
    const float* __restrict__ rmean, const float* __restrict__ rvar)
{
    const int N = 128, K = 576;
    __shared__ float As[16][64];
    __shared__ float Bs[16][64];
    int m0 = blockIdx.x*64, n0 = blockIdx.y*64;
    int tid = threadIdx.x;
    int ty = tid >> 4, tx = tid & 15;
    unsigned long long acc[4][2];
#pragma unroll
    for (int i=0;i<4;i++){ acc[i][0]=0ull; acc[i][1]=0ull; }
    int ar = tid >> 2, ac = (tid & 3) << 2;
    int wr = tid >> 4, wc = (tid & 15) << 2;
    int nodeA = perm ? perm[m0 + ar] : (m0 + ar);
    const float* Ah = h2 + (size_t)nodeA*512 + ac;
    const float* At = T  + (size_t)nodeA*64 + ac;
    const float* Wptr = Wc + (size_t)wr*N + n0+wc;

    float4 av = *(const float4*)(Ah);
    float4 wv = *(const float4*)(Wptr);

    for (int k0=0; k0<K; k0+=16){
        As[ac+0][ar]=av.x; As[ac+1][ar]=av.y; As[ac+2][ar]=av.z; As[ac+3][ar]=av.w;
        *(float4*)&Bs[wr][wc] = wv;
        __syncthreads();
        int k1 = k0 + 16;
        if (k1 < K){
            av = (k1 < 512) ? *(const float4*)(Ah + k1)
                            : *(const float4*)(At + (k1-512));
            wv = *(const float4*)(Wptr + (size_t)k1*N);
        }
#pragma unroll
        for (int kk=0; kk<16; ++kk){
            float4 ra = *(const float4*)&As[kk][ty*4];
            ulonglong2 rb = *(const ulonglong2*)&Bs[kk][tx*4];
            unsigned long long rp[4];
            DUP2(rp[0], ra.x); DUP2(rp[1], ra.y); DUP2(rp[2], ra.z); DUP2(rp[3], ra.w);
#pragma unroll
            for (int i=0;i<4;i++){
                FFMA2(acc[i][0], rp[i], rb.x);
                FFMA2(acc[i][1], rp[i], rb.y);
            }
        }
        __syncthreads();
    }
#pragma unroll
    for (int i=0;i<4;i++){
        int nodeC = perm ? perm[m0+ty*4+i] : (m0+ty*4+i);
#pragma unroll
        for (int j=0;j<4;j++){
            int n = n0 + tx*4 + j;
            float2 p = *(float2*)&acc[i][j>>1];
            float c = ((j&1) ? p.y : p.x) + bias[n];
            c = fmaxf(c, 0.f);
            c = (c - rmean[n]) * rsqrtf(rvar[n] + 1e-5f) * gamma[n] + beta[n];
            C[(size_t)nodeC*N + n] = c;
        }
    }
}

// ---------------- fused attention (no We epilogue; outputs h2core + T) ----------------
__global__ void __launch_bounds__(128) fused_attn(
    const float* __restrict__ q, const float* __restrict__ k,
    const float* __restrict__ v, const float* __restrict__ xr,
    const float* __restrict__ P, const float* __restrict__ eattr,
    const float* __restrict__ Wb, const float* __restrict__ WbWeL,
    const int* __restrict__ csr, const int* __restrict__ row,
    const int* __restrict__ src, const int* __restrict__ perm, int nlive,
    float* __restrict__ h2, float* __restrict__ Tout)
{
    __shared__ float sS[4][CHUNK];
    __shared__ float red[4];
    __shared__ float btaSh;
    int tid  = threadIdx.x;
    int warp = tid >> 5, lane = tid & 31;
    int off  = warp*128 + lane*4;      // head = warp
    float wbwe_reg = (lane < 16) ? WbWeL[warp*16 + lane] : 0.f;

    for (int ni = blockIdx.x; ni < nlive; ni += gridDim.x){
        int n = perm ? perm[ni] : ni;
        __syncthreads();
        int r0 = row[n], r1 = row[n+1];
        float4 qf = *(const float4*)(q + (size_t)n*HDC + off);
        float Pj = (lane < 16) ? P[(size_t)n*64 + warp*16 + lane] : 0.f;

        float m = -1e30f, den = 0.f;
        float a0=0.f,a1=0.f,a2=0.f,a3=0.f;
        float Te = 0.f;

        for (int c0 = r0; c0 < r1; c0 += CHUNK){
            int cnt = min(CHUNK, r1 - c0);
            int i = 0;
            for (; i+1 < cnt; i += 2){
                int ea_ = csr[c0+i], eb_ = csr[c0+i+1];
                int sa_ = src[ea_],  sb_ = src[eb_];
                float4 ka = *(const float4*)(k + (size_t)sa_*HDC + off);
                float4 kb = *(const float4*)(k + (size_t)sb_*HDC + off);
                float eaa = (lane < 16) ? eattr[(size_t)ea_*EDIMC + lane] : 0.f;
                float eab = (lane < 16) ? eattr[(size_t)eb_*EDIMC + lane] : 0.f;
                float pa = qf.x*ka.x + qf.y*ka.y + qf.z*ka.z + qf.w*ka.w + Pj*eaa;
                float pb = qf.x*kb.x + qf.y*kb.y + qf.z*kb.z + qf.w*kb.w + Pj*eab;
#pragma unroll
                for (int o=16;o;o>>=1){
                    pa += __shfl_xor_sync(0xffffffffu, pa, o);
                    pb += __shfl_xor_sync(0xffffffffu, pb, o);
                }
                if (lane == 0){
                    sS[warp][i]   = pa * ATTN_SCALE;
                    sS[warp][i+1] = pb * ATTN_SCALE;
                }
            }
            if (i < cnt){
                int ea_ = csr[c0+i];
                int sa_ = src[ea_];
                float4 ka = *(const float4*)(k + (size_t)sa_*HDC + off);
                float eaa = (lane < 16) ? eattr[(size_t)ea_*EDIMC + lane] : 0.f;
                float pa = qf.x*ka.x + qf.y*ka.y + qf.z*ka.z + qf.w*ka.w + Pj*eaa;
#pragma unroll
                for (int o=16;o;o>>=1) pa += __shfl_xor_sync(0xffffffffu, pa, o);
                if (lane == 0) sS[warp][i] = pa * ATTN_SCALE;
            }
            __syncwarp();
            float v0 = (lane      < cnt) ? sS[warp][lane]      : -1e30f;
            float v1 = (lane+32   < cnt) ? sS[warp][lane+32]   : -1e30f;
            float cm = fmaxf(v0, v1);
#pragma unroll
            for (int o=16;o;o>>=1) cm = fmaxf(cm, __shfl_xor_sync(0xffffffffu, cm, o));
            float mN = fmaxf(m, cm);
            float corr = expf(m - mN);
            den *= corr; a0 *= corr; a1 *= corr; a2 *= corr; a3 *= corr; Te *= corr;
            m = mN;
            float w0 = (lane    < cnt) ? expf(v0 - mN) : 0.f;
            float w1 = (lane+32 < cnt) ? expf(v1 - mN) : 0.f;
            if (lane      < cnt) sS[warp][lane]    = w0;
            if (lane+32   < cnt) sS[warp][lane+32] = w1;
            float ds = w0 + w1;
#pragma unroll
            for (int o=16;o;o>>=1) ds += __shfl_xor_sync(0xffffffffu, ds, o);
            den += ds;
            __syncwarp();
            for (int j=0; j<cnt; ++j){
                int e = csr[c0+j];
                int s = src[e];
                float w = sS[warp][j];
                float4 vf = *(const float4*)(v + (size_t)s*HDC + off);
                a0 += w*vf.x; a1 += w*vf.y; a2 += w*vf.z; a3 += w*vf.w;
                if (lane < 16) Te += w * eattr[(size_t)e*EDIMC + lane];
            }
            __syncwarp();
        }
        float inv = 1.f/fmaxf(den, 1e-16f);
        float tp  = (lane < 16) ? Te * inv : 0.f;
        float o0=a0*inv, o1=a1*inv, o2=a2*inv, o3=a3*inv;

        float4 xrf = *(const float4*)(xr + (size_t)n*HDC + off);
        const float* WbA = Wb + off;
        const float* WbB = Wb + HDC + off;
        const float* WbC = Wb + 2*HDC + off;
        float part = o0*WbA[0] + o1*WbA[1] + o2*WbA[2] + o3*WbA[3]
                   + xrf.x*WbB[0] + xrf.y*WbB[1] + xrf.z*WbB[2] + xrf.w*WbB[3]
                   + (o0-xrf.x)*WbC[0] + (o1-xrf.y)*WbC[1]
                   + (o2-xrf.z)*WbC[2] + (o3-xrf.w)*WbC[3]
                   + wbwe_reg * tp;
#pragma unroll
        for (int o=16;o;o>>=1) part += __shfl_xor_sync(0xffffffffu, part, o);
        if (lane == 0) red[warp] = part;
        __syncthreads();
        if (tid == 0) btaSh = 1.f/(1.f + expf(-(red[0]+red[1]+red[2]+red[3])));
        __syncthreads();
        float bta = btaSh;
        float* hr = h2 + (size_t)n*HDC + off;
        hr[0] = bta*xrf.x + (1.f-bta)*o0;
        hr[1] = bta*xrf.y + (1.f-bta)*o1;
        hr[2] = bta*xrf.z + (1.f-bta)*o2;
        hr[3] = bta*xrf.w + (1.f-bta)*o3;
        if (lane < 16) Tout[(size_t)n*64 + warp*16 + lane] = (1.f-bta)*tp;
    }
}

// ---------------- pooling ----------------
__global__ void pool_score(const float* __restrict__ h, const float* __restrict__ w,
                           float* __restrict__ sArr)
{
    int gw = (blockIdx.x*blockDim.x + threadIdx.x) >> 5;
    int lane = threadIdx.x & 31;
    if (gw >= NNC) return;
    const float* hr = h + (size_t)gw*FD;
    float4 hv = *(const float4*)&hr[lane*4];
    float4 wv = *(const float4*)&w[lane*4];
    float dot = hv.x*wv.x + hv.y*wv.y + hv.z*wv.z + hv.w*wv.w;
    float nw  = wv.x*wv.x + wv.y*wv.y + wv.z*wv.z + wv.w*wv.w;
#pragma unroll
    for (int off=16; off; off>>=1){
        dot += __shfl_xor_sync(0xffffffffu, dot, off);
        nw  += __shfl_xor_sync(0xffffffffu, nw , off);
    }
    if (lane == 0) sArr[gw] = tanhf(dot / sqrtf(nw));
}

__global__ void pool_rank(const float* __restrict__ sArr, int* __restrict__ nmask,
                          float* __restrict__ h, int kkeep, int* __restrict__ perm)
{
    __shared__ float ss[256];
    __shared__ float scl[256];
    __shared__ int   kp[256];
    int b = blockIdx.x, t = threadIdx.x;
    int n = b*NPG + t;
    int m0 = nmask[n];
    float sv = sArr[n];
    ss[t] = m0 ? sv : -INFINITY;
    __syncthreads();
    float mys = ss[t];
    int rank = 0;
    for (int j=0; j<NPG; ++j){
        float o = ss[j];
        rank += (o > mys) || (o == mys && j < t);
    }
    int keep = (rank < kkeep) && m0;
    nmask[n] = keep;
    scl[t] = keep ? sv : 0.f;
    kp[t]  = keep;
    __syncthreads();
    if (keep){
        int pos = 0;
        for (int j=0; j<t; ++j) pos += kp[j];
        perm[b*kkeep + pos] = n;
    }
    for (int idx=t; idx<NPG*FD; idx+=256){
        int ln = idx >> 7, f = idx & 127;
        h[(size_t)(b*NPG+ln)*FD + f] *= scl[ln];
    }
}

__global__ void pool_readout(const float* __restrict__ h, const int* __restrict__ nmask,
                             float* __restrict__ rep, int first)
{
    int b = blockIdx.x, f = threadIdx.x;
    float mx = -1e30f, sm = 0.f, cnt = 0.f;
    for (int j=0; j<NPG; ++j){
        int n = b*NPG + j;
        int kp = nmask[n];
        float hv = h[(size_t)n*FD + f];
        mx = fmaxf(mx, kp ? hv : -1e30f);
        sm += hv;
        cnt += kp ? 1.f : 0.f;
    }
    float gmean = sm / fmaxf(cnt, 1.f);
    int o = b*256 + f;
    if (first){ rep[o] = mx; rep[o+128] = gmean; }
    else      { rep[o] += mx; rep[o+128] += gmean; }
}

// ---------------- head MLP ----------------
__global__ void assemble_kernel(const float* __restrict__ rep, const float* __restrict__ esm,
                                float* __restrict__ gin)
{
    int idx = blockIdx.x*blockDim.x + threadIdx.x;
    if (idx >= BGR*1536) return;
    int b = idx / 1536, c = idx % 1536;
    gin[idx] = (c < 256) ? rep[b*256 + c] : esm[(size_t)b*ESMC + (c-256)];
}

__global__ void mlp_kernel(const float* __restrict__ A, const float* __restrict__ W,
                           const float* __restrict__ bias, float* __restrict__ C,
                           int Kd, int Nd, int doRelu)
{
    int b = blockIdx.x;
    for (int n = threadIdx.x; n < Nd; n += blockDim.x){
        float acc = 0.f;
        for (int k=0; k<Kd; ++k) acc += A[(size_t)b*Kd + k] * W[(size_t)k*Nd + n];
        acc += bias[n];
        if (doRelu) acc = fmaxf(acc, 0.f);
        C[(size_t)b*Nd + n] = acc;
    }
}

// ---------------- host orchestration ----------------
template<typename T> static T* symaddr(const void* sym){
    void* p = nullptr; cudaGetSymbolAddress(&p, sym); return (T*)p;
}

extern "C" void kernel_launch(void* const* d_in, const int* in_sizes, int n_in,
                              void* d_out, int out_size)
{
    (void)in_sizes; (void)n_in; (void)out_size;
    const float* x      = (const float*)d_in[0];
    const float* eattr  = (const float*)d_in[1];
    const int*   eidx   = (const int*)  d_in[2];
    const float* esm    = (const float*)d_in[4];
    const float* Wq     = (const float*)d_in[5];
    const float* bq     = (const float*)d_in[6];
    const float* Wk     = (const float*)d_in[7];
    const float* bk     = (const float*)d_in[8];
    const float* Wv     = (const float*)d_in[9];
    const float* bv     = (const float*)d_in[10];
    const float* We     = (const float*)d_in[11];
    const float* Wskip  = (const float*)d_in[12];
    const float* bskip  = (const float*)d_in[13];
    const float* Wbeta  = (const float*)d_in[14];
    const float* Wt     = (const float*)d_in[15];
    const float* bt     = (const float*)d_in[16];
    const float* gamma  = (const float*)d_in[17];
    const float* betaBN = (const float*)d_in[18];
    const float* rmean  = (const float*)d_in[19];
    const float* rvar   = (const float*)d_in[20];
    const float* pw     = (const float*)d_in[21];
    const float* W1     = (const float*)d_in[22];
    const float* b1     = (const float*)d_in[23];
    const float* W2     = (const float*)d_in[24];
    const float* b2     = (const float*)d_in[25];
    const float* W3     = (const float*)d_in[26];
    const float* b3     = (const float*)d_in[27];

    const int* src = eidx;
    const int* dst = eidx + EC;

    float* q_    = symaddr<float>(g_q);
    float* k_    = symaddr<float>(g_k);
    float* v_    = symaddr<float>(g_v);
    float* xr_   = symaddr<float>(g_xr);
    float* h2_   = symaddr<float>(g_h2);
    float* P_    = symaddr<float>(g_P);
    float* T_    = symaddr<float>(g_T);
    float* hA_   = symaddr<float>(g_hA);
    float* hB_   = symaddr<float>(g_hB);
    int* deg_    = symaddr<int>(g_deg);
    int* row_    = symaddr<int>(g_row);
    int* csr_    = symaddr<int>(g_csr);
    int* nm_     = symaddr<int>(g_nmask);
    int* perm_   = symaddr<int>(g_perm);
    float* s_    = symaddr<float>(g_s);
    float* rep_  = symaddr<float>(g_rep);
    float* gin_  = symaddr<float>(g_gin);
    float* m1_   = symaddr<float>(g_m1);
    float* m2_   = symaddr<float>(g_m2);
    float* Wqe_  = symaddr<float>(g_Wqe);
    float* bPe_  = symaddr<float>(g_bPe);
    float* Wc_   = symaddr<float>(g_Wcomb);
    float* WbWe_ = symaddr<float>(g_WbWe);

    // precompute folded weights (deterministic; depends only on inputs)
    prec_wqe  <<<(5*128*512+255)/256, 256>>>(Wq, We, Wqe_);
    prec_bpe  <<<(5*128+255)/256, 256>>>(bq, We, bPe_);
    prec_wcomb<<<(5*576*128+255)/256, 256>>>(Wt, We, Wc_);

    const float* hin = x;
    float* bufs[2] = { hA_, hB_ };
    const int Mli[5] = { NNC, NNC, NNC/2, NNC/2, NNC/4 };

    for (int li=0; li<5; ++li){
        const float* WqL = Wq + (size_t)li*FD*HDC;
        const float* WkL = Wk + (size_t)li*FD*HDC;
        const float* WvL = Wv + (size_t)li*FD*HDC;
        const float* WsL = Wskip + (size_t)li*FD*HDC;
        const float* WbL = Wbeta + (size_t)li*3*HDC;
        int M = Mli[li];
        const int* pm = (li < 2) ? nullptr : perm_;

        gemm_qkvs<<<dim3(M/128, 17), 256>>>(hin, pm,
            WqL, WkL, WvL, WsL, Wqe_ + (size_t)li*128*512,
            bq + li*HDC, bk + li*HDC, bv + li*HDC, bskip + li*HDC, bPe_ + li*128,
            q_, k_, v_, xr_, P_);

        if (li == 0){
            prec_wbwe<<<(5*64+255)/256, 256>>>(We, Wbeta, WbWe_);
            k_init <<<NNC/256, 256>>>(deg_, nm_, 1);
            k_count<<<EC/256, 256>>>(src, dst, nm_, 0, deg_);
            k_scan <<<1, 256>>>(deg_, row_, deg_);
            k_fill <<<EC/256, 256>>>(src, dst, nm_, 0, deg_, csr_);
        }

        fused_attn<<<2048, 128>>>(q_, k_, v_, xr_, P_, eattr,
                                  WbL, WbWe_ + li*64,
                                  csr_, row_, src, pm, M, h2_, T_);

        float* hout = bufs[li & 1];
        gemm64<<<dim3(M/64, FD/64), 256>>>(h2_, T_, pm,
            Wc_ + (size_t)li*576*128, bt + li*FD, hout,
            gamma + li*FD, betaBN + li*FD, rmean + li*FD, rvar + li*FD);
        hin = hout;

        if (li == 1 || li == 3){
            int p = (li == 1) ? 0 : 1;
            int kkeep = (p == 0) ? NPG/2 : NPG/4;
            pool_score  <<<NNC/8, 256>>>(hout, pw + p*FD, s_);
            pool_rank   <<<BGR, 256>>>(s_, nm_, hout, kkeep, perm_);
            pool_readout<<<BGR, 128>>>(hout, nm_, rep_, p == 0);
            k_init <<<NNC/256, 256>>>(deg_, nm_, 0);
            k_count<<<EC/256, 256>>>(src, dst, nm_, 1, deg_);
            k_scan <<<1, 256>>>(deg_, row_, deg_);
            k_fill <<<EC/256, 256>>>(src, dst, nm_, 1, deg_, csr_);
        }
    }

    assemble_kernel<<<(BGR*1536)/256, 256>>>(rep_, esm, gin_);
    mlp_kernel<<<BGR, 256>>>(gin_, W1, b1, m1_, 1536, 512, 1);
    mlp_kernel<<<BGR, 256>>>(m1_,  W2, b2, m2_, 512, 256, 1);
    mlp_kernel<<<BGR, 32>>>(m2_,  W3, b3, (float*)d_out, 256, 10, 0);
}

// round 13
// speedup vs baseline: 1.0505x; 1.0505x over previous
#include <cuda_runtime.h>
#include <cuda_bf16.h>
#include <math.h>

// ---------------- problem constants ----------------
#define BGR   32
#define NPG   256
#define NNC   8192
#define EC    65536
#define FD    128
#define EDIMC 16
#define ESMC  1280
#define HC    4
#define DHC   128
#define HDC   512
#define ATTN_SCALE 0.08838834764831845f  // 1/sqrt(128)
#define CHUNK 64

// packed fp32 helpers (Blackwell f32x2 pipe — 2 FMAs per issue)
#define FFMA2(d,a,b) asm("fma.rn.f32x2 %0, %1, %2, %0;" : "+l"(d) : "l"(a), "l"(b))
#define DUP2(d,s)    asm("mov.b64 %0, {%1, %1};" : "=l"(d) : "f"(s))

// ---------------- device scratch ----------------
__device__ float g_q [NNC*HDC];
__device__ float g_k [NNC*HDC];
__device__ float g_v [NNC*HDC];
__device__ float g_xr[NNC*HDC];
__device__ float g_h2[NNC*HDC];
__device__ float g_P [NNC*64];
__device__ float g_T [NNC*64];
__device__ float g_hA[NNC*FD];
__device__ float g_hB[NNC*FD];
__device__ int   g_deg[NNC];
__device__ int   g_row[NNC+1];
__device__ int   g_csr[EC];
__device__ int   g_nmask[NNC];
__device__ int   g_perm[NNC];
__device__ float g_s[NNC];
__device__ float g_rep[BGR*256];
__device__ float g_gin[BGR*1536];
__device__ float g_m1[BGR*512];
__device__ float g_m2[BGR*256];
// precomputed weight folds
__device__ float g_Wqe [5*128*512];   // padded: cols 0..63 real, rest 0
__device__ float g_bPe [5*128];
__device__ float g_Wcomb[5*576*128];  // rows 0..511 = Wt, rows 512.. = We@Wt
__device__ float g_WbWe [5*64];

// ---------------- precompute kernels ----------------
__global__ void prec_wqe(const float* __restrict__ Wq, const float* __restrict__ We,
                         float* __restrict__ Wqe)
{
    int idx = blockIdx.x*blockDim.x + threadIdx.x;
    if (idx >= 5*128*512) return;
    int li = idx / 65536;
    int r  = idx % 65536;
    int kk = r / 512, c = r % 512;
    float val = 0.f;
    if (c < 64){
        int h = c >> 4, j = c & 15;
        const float* a = Wq + (size_t)li*128*512 + (size_t)kk*512 + h*128;
        const float* b = We + (size_t)li*16*512 + (size_t)j*512 + h*128;
        for (int d=0; d<128; ++d) val += a[d]*b[d];
    }
    Wqe[idx] = val;
}
__global__ void prec_bpe(const float* __restrict__ bq, const float* __restrict__ We,
                         float* __restrict__ bPe)
{
    int idx = blockIdx.x*blockDim.x + threadIdx.x;
    if (idx >= 5*128) return;
    int li = idx / 128, c = idx % 128;
    float val = 0.f;
    if (c < 64){
        int h = c >> 4, j = c & 15;
        const float* a = bq + (size_t)li*512 + h*128;
        const float* b = We + (size_t)li*16*512 + (size_t)j*512 + h*128;
        for (int d=0; d<128; ++d) val += a[d]*b[d];
    }
    bPe[idx] = val;
}
__global__ void prec_wcomb(const float* __restrict__ Wt, const float* __restrict__ We,
                           float* __restrict__ Wc)
{
    int idx = blockIdx.x*blockDim.x + threadIdx.x;
    if (idx >= 5*576*128) return;
    int li = idx / (576*128);
    int r  = idx % (576*128);
    int rowk = r / 128, f = r % 128;
    float val;
    if (rowk < 512){
        val = Wt[(size_t)li*512*128 + (size_t)rowk*128 + f];
    } else {
        int c = rowk - 512;
        int h = c >> 4, j = c & 15;
        const float* we = We + (size_t)li*16*512 + (size_t)j*512 + h*128;
        const float* wt = Wt + (size_t)li*512*128 + (size_t)(h*128)*128 + f;
        float s = 0.f;
        for (int d=0; d<128; ++d) s += we[d]*wt[(size_t)d*128];
        val = s;
    }
    Wc[idx] = val;
}
__global__ void prec_wbwe(const float* __restrict__ We, const float* __restrict__ Wbeta,
                          float* __restrict__ WbWe)
{
    int idx = blockIdx.x*blockDim.x + threadIdx.x;
    if (idx >= 5*64) return;
    int li = idx / 64, c = idx % 64;
    int h = c >> 4, j = c & 15;
    const float* we = We + (size_t)li*16*512 + (size_t)j*512 + h*128;
    const float* w1 = Wbeta + (size_t)li*1536 + h*128;
    const float* w3 = Wbeta + (size_t)li*1536 + 1024 + h*128;
    float s = 0.f;
    for (int d=0; d<128; ++d) s += we[d]*(w1[d]+w3[d]);
    WbWe[idx] = s;
}

// ---------------- CSR build ----------------
__global__ void k_init(int* deg, int* nmask, int initMask){
    int i = blockIdx.x*blockDim.x + threadIdx.x;
    if (i < NNC){ deg[i]=0; if (initMask) nmask[i]=1; }
}
__global__ void k_count(const int* __restrict__ src, const int* __restrict__ dst,
                        const int* __restrict__ nmask, int useMask, int* deg){
    int e = blockIdx.x*blockDim.x + threadIdx.x;
    if (e < EC){
        int d = dst[e];
        if (!useMask || (nmask[d] && nmask[src[e]])) atomicAdd(&deg[d], 1);
    }
}
__global__ void k_scan(int* deg, int* row, int* cur){
    __shared__ int part[256];
    int t = threadIdx.x;
    int base = t*32;
    int loc[32];
    int s = 0;
    for (int i=0;i<32;i++){ loc[i] = deg[base+i]; s += loc[i]; }
    part[t] = s;
    __syncthreads();
    if (t == 0){
        int run = 0;
        for (int i=0;i<256;i++){ int tmp = part[i]; part[i] = run; run += tmp; }
    }
    __syncthreads();
    int run = part[t];
    for (int i=0;i<32;i++){ row[base+i] = run; cur[base+i] = run; run += loc[i]; }
    if (t == 255) row[NNC] = run;
}
__global__ void k_fill(const int* __restrict__ src, const int* __restrict__ dst,
                       const int* __restrict__ nmask, int useMask,
                       int* cur, int* csr){
    int e = blockIdx.x*blockDim.x + threadIdx.x;
    if (e < EC){
        int d = dst[e];
        if (!useMask || (nmask[d] && nmask[src[e]])){
            int pos = atomicAdd(&cur[d], 1);
            csr[pos] = e;
        }
    }
}

// ---------------- GEMM: fused Q/K/V/skip/P (5 segments), f32x2, single-buffer ----------------
__global__ void __launch_bounds__(256, 2) gemm_qkvs(
    const float* __restrict__ A, const int* __restrict__ perm,
    const float* __restrict__ W0,const float* __restrict__ W1,
    const float* __restrict__ W2,const float* __restrict__ W3,
    const float* __restrict__ Wp,
    const float* __restrict__ b0,const float* __restrict__ b1,
    const float* __restrict__ b2,const float* __restrict__ b3,
    const float* __restrict__ bP,
    float* __restrict__ C0,float* __restrict__ C1,
    float* __restrict__ C2,float* __restrict__ C3,
    float* __restrict__ CP)
{
    const int K = 128, NW = 512;
    int y   = blockIdx.y;
    int seg = y >> 2;                 // 0..4 (y==16 -> seg 4)
    int n0  = (y & 3) << 7;
    const float* W; const float* bias;
    if      (seg==0){ W=W0; bias=b0; }
    else if (seg==1){ W=W1; bias=b1; }
    else if (seg==2){ W=W2; bias=b2; }
    else if (seg==3){ W=W3; bias=b3; }
    else            { W=Wp; bias=bP; }
    int m0 = blockIdx.x << 7;

    __shared__ float As[16][128];
    __shared__ float Bs[16][128];
    int tid = threadIdx.x;
    int tr = (tid >> 4) << 3;
    int tc = (tid & 15) << 3;
    unsigned long long acc[8][4];
#pragma unroll
    for (int i=0;i<8;i++)
#pragma unroll
        for (int j=0;j<4;j++) acc[i][j]=0ull;

    int ar = tid >> 1, ac = (tid & 1) << 3;
    int wr = tid >> 4, wc = (tid & 15) << 3;
    int nodeA = perm ? perm[m0 + ar] : (m0 + ar);
    const float* Aptr = A + (size_t)nodeA*K + ac;
    const float* Wptr = W + (size_t)wr*NW + n0+wc;

    float4 av0 = *(const float4*)(Aptr);
    float4 av1 = *(const float4*)(Aptr+4);
    float4 bv0 = *(const float4*)(Wptr);
    float4 bv1 = *(const float4*)(Wptr+4);

    for (int k0=0; k0<K; k0+=16){
        As[ac+0][ar]=av0.x; As[ac+1][ar]=av0.y; As[ac+2][ar]=av0.z; As[ac+3][ar]=av0.w;
        As[ac+4][ar]=av1.x; As[ac+5][ar]=av1.y; As[ac+6][ar]=av1.z; As[ac+7][ar]=av1.w;
        *(float4*)&Bs[wr][wc]   = bv0;
        *(float4*)&Bs[wr][wc+4] = bv1;
        __syncthreads();
        if (k0+16 < K){
            av0 = *(const float4*)(Aptr + k0+16);
            av1 = *(const float4*)(Aptr + k0+20);
            bv0 = *(const float4*)(Wptr + (size_t)(k0+16)*NW);
            bv1 = *(const float4*)(Wptr + (size_t)(k0+16)*NW + 4);
        }
#pragma unroll
        for (int kk=0; kk<16; ++kk){
            float4 ra0 = *(const float4*)&As[kk][tr];
            float4 ra1 = *(const float4*)&As[kk][tr+4];
            ulonglong2 rbA = *(const ulonglong2*)&Bs[kk][tc];
            ulonglong2 rbB = *(const ulonglong2*)&Bs[kk][tc+4];
            unsigned long long rp[8];
            DUP2(rp[0], ra0.x); DUP2(rp[1], ra0.y); DUP2(rp[2], ra0.z); DUP2(rp[3], ra0.w);
            DUP2(rp[4], ra1.x); DUP2(rp[5], ra1.y); DUP2(rp[6], ra1.z); DUP2(rp[7], ra1.w);
#pragma unroll
            for (int i=0;i<8;i++){
                FFMA2(acc[i][0], rp[i], rbA.x);
                FFMA2(acc[i][1], rp[i], rbA.y);
                FFMA2(acc[i][2], rp[i], rbB.x);
                FFMA2(acc[i][3], rp[i], rbB.y);
            }
        }
        __syncthreads();
    }
    if (seg < 4){
        float* C = seg==0?C0: seg==1?C1: seg==2?C2:C3;
#pragma unroll
        for (int i=0;i<8;i++){
            int nodeC = perm ? perm[m0+tr+i] : (m0+tr+i);
            float* Crow = C + (size_t)nodeC*NW + n0+tc;
#pragma unroll
            for (int j=0;j<4;j++){
                float2 p = *(float2*)&acc[i][j];
                Crow[2*j+0] = p.x + bias[n0+tc+2*j+0];
                Crow[2*j+1] = p.y + bias[n0+tc+2*j+1];
            }
        }
    } else if (tc < 64){
#pragma unroll
        for (int i=0;i<8;i++){
            int nodeC = perm ? perm[m0+tr+i] : (m0+tr+i);
            float* Crow = CP + (size_t)nodeC*64 + tc;
#pragma unroll
            for (int j=0;j<4;j++){
                float2 p = *(float2*)&acc[i][j];
                Crow[2*j+0] = p.x + bias[tc+2*j+0];
                Crow[2*j+1] = p.y + bias[tc+2*j+1];
            }
        }
    }
}

// ---------------- GEMM 64x64, K=576 (h2core | T), ReLU+BN epilogue ----------------
__global__ void __launch_bounds__(256) gemm64(
    const float* __restrict__ h2, const float* __restrict__ T,
    const int* __restrict__ perm,
    const float* __restrict__ Wc, const float* __restrict__ bias,
    float* __restrict__ C,
    const float* __restrict__ gamma, const float* __restrict__ beta,
    const float* __restrict__ rmean, const float* __restrict__ rvar)
{
    const int N = 128, K = 576;
    __shared__ float As[16][64];
    __shared__ float Bs[16][64];
    int m0 = blockIdx.x*64, n0 = blockIdx.y*64;
    int tid = threadIdx.x;
    int ty = tid >> 4, tx = tid & 15;
    unsigned long long acc[4][2];
#pragma unroll
    for (int i=0;i<4;i++){ acc[i][0]=0ull; acc[i][1]=0ull; }
    int ar = tid >> 2, ac = (tid & 3) << 2;
    int wr = tid >> 4, wc = (tid & 15) << 2;
    int nodeA = perm ? perm[m0 + ar] : (m0 + ar);
    const float* Ah = h2 + (size_t)nodeA*512 + ac;
    const float* At = T  + (size_t)nodeA*64 + ac;
    const float* Wptr = Wc + (size_t)wr*N + n0+wc;

    float4 av = *(const float4*)(Ah);
    float4 wv = *(const float4*)(Wptr);

    for (int k0=0; k0<K; k0+=16){
        As[ac+0][ar]=av.x; As[ac+1][ar]=av.y; As[ac+2][ar]=av.z; As[ac+3][ar]=av.w;
        *(float4*)&Bs[wr][wc] = wv;
        __syncthreads();
        int k1 = k0 + 16;
        if (k1 < K){
            av = (k1 < 512) ? *(const float4*)(Ah + k1)
                            : *(const float4*)(At + (k1-512));
            wv = *(const float4*)(Wptr + (size_t)k1*N);
        }
#pragma unroll
        for (int kk=0; kk<16; ++kk){
            float4 ra = *(const float4*)&As[kk][ty*4];
            ulonglong2 rb = *(const ulonglong2*)&Bs[kk][tx*4];
            unsigned long long rp[4];
            DUP2(rp[0], ra.x); DUP2(rp[1], ra.y); DUP2(rp[2], ra.z); DUP2(rp[3], ra.w);
#pragma unroll
            for (int i=0;i<4;i++){
                FFMA2(acc[i][0], rp[i], rb.x);
                FFMA2(acc[i][1], rp[i], rb.y);
            }
        }
        __syncthreads();
    }
#pragma unroll
    for (int i=0;i<4;i++){
        int nodeC = perm ? perm[m0+ty*4+i] : (m0+ty*4+i);
#pragma unroll
        for (int j=0;j<4;j++){
            int n = n0 + tx*4 + j;
            float2 p = *(float2*)&acc[i][j>>1];
            float c = ((j&1) ? p.y : p.x) + bias[n];
            c = fmaxf(c, 0.f);
            c = (c - rmean[n]) * rsqrtf(rvar[n] + 1e-5f) * gamma[n] + beta[n];
            C[(size_t)nodeC*N + n] = c;
        }
    }
}

// ---------------- fused attention (no We epilogue; outputs h2core + T) ----------------
__global__ void __launch_bounds__(128) fused_attn(
    const float* __restrict__ q, const float* __restrict__ k,
    const float* __restrict__ v, const float* __restrict__ xr,
    const float* __restrict__ P, const float* __restrict__ eattr,
    const float* __restrict__ Wb, const float* __restrict__ WbWeL,
    const int* __restrict__ csr, const int* __restrict__ row,
    const int* __restrict__ src, const int* __restrict__ perm, int nlive,
    float* __restrict__ h2, float* __restrict__ Tout)
{
    __shared__ float sS[4][CHUNK];
    __shared__ float red[4];
    __shared__ float btaSh;
    int tid  = threadIdx.x;
    int warp = tid >> 5, lane = tid & 31;
    int off  = warp*128 + lane*4;      // head = warp
    float wbwe_reg = (lane < 16) ? WbWeL[warp*16 + lane] : 0.f;

    for (int ni = blockIdx.x; ni < nlive; ni += gridDim.x){
        int n = perm ? perm[ni] : ni;
        __syncthreads();
        int r0 = row[n], r1 = row[n+1];
        float4 qf = *(const float4*)(q + (size_t)n*HDC + off);
        float Pj = (lane < 16) ? P[(size_t)n*64 + warp*16 + lane] : 0.f;

        float m = -1e30f, den = 0.f;
        float a0=0.f,a1=0.f,a2=0.f,a3=0.f;
        float Te = 0.f;

        for (int c0 = r0; c0 < r1; c0 += CHUNK){
            int cnt = min(CHUNK, r1 - c0);
            int i = 0;
            for (; i+1 < cnt; i += 2){
                int ea_ = csr[c0+i], eb_ = csr[c0+i+1];
                int sa_ = src[ea_],  sb_ = src[eb_];
                float4 ka = *(const float4*)(k + (size_t)sa_*HDC + off);
                float4 kb = *(const float4*)(k + (size_t)sb_*HDC + off);
                float eaa = (lane < 16) ? eattr[(size_t)ea_*EDIMC + lane] : 0.f;
                float eab = (lane < 16) ? eattr[(size_t)eb_*EDIMC + lane] : 0.f;
                float pa = qf.x*ka.x + qf.y*ka.y + qf.z*ka.z + qf.w*ka.w + Pj*eaa;
                float pb = qf.x*kb.x + qf.y*kb.y + qf.z*kb.z + qf.w*kb.w + Pj*eab;
#pragma unroll
                for (int o=16;o;o>>=1){
                    pa += __shfl_xor_sync(0xffffffffu, pa, o);
                    pb += __shfl_xor_sync(0xffffffffu, pb, o);
                }
                if (lane == 0){
                    sS[warp][i]   = pa * ATTN_SCALE;
                    sS[warp][i+1] = pb * ATTN_SCALE;
                }
            }
            if (i < cnt){
                int ea_ = csr[c0+i];
                int sa_ = src[ea_];
                float4 ka = *(const float4*)(k + (size_t)sa_*HDC + off);
                float eaa = (lane < 16) ? eattr[(size_t)ea_*EDIMC + lane] : 0.f;
                float pa = qf.x*ka.x + qf.y*ka.y + qf.z*ka.z + qf.w*ka.w + Pj*eaa;
#pragma unroll
                for (int o=16;o;o>>=1) pa += __shfl_xor_sync(0xffffffffu, pa, o);
                if (lane == 0) sS[warp][i] = pa * ATTN_SCALE;
            }
            __syncwarp();
            float v0 = (lane      < cnt) ? sS[warp][lane]      : -1e30f;
            float v1 = (lane+32   < cnt) ? sS[warp][lane+32]   : -1e30f;
            float cm = fmaxf(v0, v1);
#pragma unroll
            for (int o=16;o;o>>=1) cm = fmaxf(cm, __shfl_xor_sync(0xffffffffu, cm, o));
            float mN = fmaxf(m, cm);
            float corr = expf(m - mN);
            den *= corr; a0 *= corr; a1 *= corr; a2 *= corr; a3 *= corr; Te *= corr;
            m = mN;
            float w0 = (lane    < cnt) ? expf(v0 - mN) : 0.f;
            float w1 = (lane+32 < cnt) ? expf(v1 - mN) : 0.f;
            if (lane      < cnt) sS[warp][lane]    = w0;
            if (lane+32   < cnt) sS[warp][lane+32] = w1;
            float ds = w0 + w1;
#pragma unroll
            for (int o=16;o;o>>=1) ds += __shfl_xor_sync(0xffffffffu, ds, o);
            den += ds;
            __syncwarp();
            for (int j=0; j<cnt; ++j){
                int e = csr[c0+j];
                int s = src[e];
                float w = sS[warp][j];
                float4 vf = *(const float4*)(v + (size_t)s*HDC + off);
                a0 += w*vf.x; a1 += w*vf.y; a2 += w*vf.z; a3 += w*vf.w;
                if (lane < 16) Te += w * eattr[(size_t)e*EDIMC + lane];
            }
            __syncwarp();
        }
        float inv = 1.f/fmaxf(den, 1e-16f);
        float tp  = (lane < 16) ? Te * inv : 0.f;
        float o0=a0*inv, o1=a1*inv, o2=a2*inv, o3=a3*inv;

        float4 xrf = *(const float4*)(xr + (size_t)n*HDC + off);
        const float* WbA = Wb + off;
        const float* WbB = Wb + HDC + off;
        const float* WbC = Wb + 2*HDC + off;
        float part = o0*WbA[0] + o1*WbA[1] + o2*WbA[2] + o3*WbA[3]
                   + xrf.x*WbB[0] + xrf.y*WbB[1] + xrf.z*WbB[2] + xrf.w*WbB[3]
                   + (o0-xrf.x)*WbC[0] + (o1-xrf.y)*WbC[1]
                   + (o2-xrf.z)*WbC[2] + (o3-xrf.w)*WbC[3]
                   + wbwe_reg * tp;
#pragma unroll
        for (int o=16;o;o>>=1) part += __shfl_xor_sync(0xffffffffu, part, o);
        if (lane == 0) red[warp] = part;
        __syncthreads();
        if (tid == 0) btaSh = 1.f/(1.f + expf(-(red[0]+red[1]+red[2]+red[3])));
        __syncthreads();
        float bta = btaSh;
        float* hr = h2 + (size_t)n*HDC + off;
        hr[0] = bta*xrf.x + (1.f-bta)*o0;
        hr[1] = bta*xrf.y + (1.f-bta)*o1;
        hr[2] = bta*xrf.z + (1.f-bta)*o2;
        hr[3] = bta*xrf.w + (1.f-bta)*o3;
        if (lane < 16) Tout[(size_t)n*64 + warp*16 + lane] = (1.f-bta)*tp;
    }
}

// ---------------- pooling ----------------
__global__ void pool_score(const float* __restrict__ h, const float* __restrict__ w,
                           float* __restrict__ sArr)
{
    int gw = (blockIdx.x*blockDim.x + threadIdx.x) >> 5;
    int lane = threadIdx.x & 31;
    if (gw >= NNC) return;
    const float* hr = h + (size_t)gw*FD;
    float4 hv = *(const float4*)&hr[lane*4];
    float4 wv = *(const float4*)&w[lane*4];
    float dot = hv.x*wv.x + hv.y*wv.y + hv.z*wv.z + hv.w*wv.w;
    float nw  = wv.x*wv.x + wv.y*wv.y + wv.z*wv.z + wv.w*wv.w;
#pragma unroll
    for (int off=16; off; off>>=1){
        dot += __shfl_xor_sync(0xffffffffu, dot, off);
        nw  += __shfl_xor_sync(0xffffffffu, nw , off);
    }
    if (lane == 0) sArr[gw] = tanhf(dot / sqrtf(nw));
}

__global__ void pool_rank(const float* __restrict__ sArr, int* __restrict__ nmask,
                          float* __restrict__ h, int kkeep, int* __restrict__ perm)
{
    __shared__ float ss[256];
    __shared__ float scl[256];
    __shared__ int   kp[256];
    int b = blockIdx.x, t = threadIdx.x;
    int n = b*NPG + t;
    int m0 = nmask[n];
    float sv = sArr[n];
    ss[t] = m0 ? sv : -INFINITY;
    __syncthreads();
    float mys = ss[t];
    int rank = 0;
    for (int j=0; j<NPG; ++j){
        float o = ss[j];
        rank += (o > mys) || (o == mys && j < t);
    }
    int keep = (rank < kkeep) && m0;
    nmask[n] = keep;
    scl[t] = keep ? sv : 0.f;
    kp[t]  = keep;
    __syncthreads();
    if (keep){
        int pos = 0;
        for (int j=0; j<t; ++j) pos += kp[j];
        perm[b*kkeep + pos] = n;
    }
    for (int idx=t; idx<NPG*FD; idx+=256){
        int ln = idx >> 7, f = idx & 127;
        h[(size_t)(b*NPG+ln)*FD + f] *= scl[ln];
    }
}

__global__ void pool_readout(const float* __restrict__ h, const int* __restrict__ nmask,
                             float* __restrict__ rep, int first)
{
    int b = blockIdx.x, f = threadIdx.x;
    float mx = -1e30f, sm = 0.f, cnt = 0.f;
    for (int j=0; j<NPG; ++j){
        int n = b*NPG + j;
        int kp = nmask[n];
        float hv = h[(size_t)n*FD + f];
        mx = fmaxf(mx, kp ? hv : -1e30f);
        sm += hv;
        cnt += kp ? 1.f : 0.f;
    }
    float gmean = sm / fmaxf(cnt, 1.f);
    int o = b*256 + f;
    if (first){ rep[o] = mx; rep[o+128] = gmean; }
    else      { rep[o] += mx; rep[o+128] += gmean; }
}

// ---------------- head MLP ----------------
__global__ void assemble_kernel(const float* __restrict__ rep, const float* __restrict__ esm,
                                float* __restrict__ gin)
{
    int idx = blockIdx.x*blockDim.x + threadIdx.x;
    if (idx >= BGR*1536) return;
    int b = idx / 1536, c = idx % 1536;
    gin[idx] = (c < 256) ? rep[b*256 + c] : esm[(size_t)b*ESMC + (c-256)];
}

__global__ void mlp_kernel(const float* __restrict__ A, const float* __restrict__ W,
                           const float* __restrict__ bias, float* __restrict__ C,
                           int Kd, int Nd, int doRelu)
{
    int b = blockIdx.x;
    for (int n = threadIdx.x; n < Nd; n += blockDim.x){
        float acc = 0.f;
        for (int k=0; k<Kd; ++k) acc += A[(size_t)b*Kd + k] * W[(size_t)k*Nd + n];
        acc += bias[n];
        if (doRelu) acc = fmaxf(acc, 0.f);
        C[(size_t)b*Nd + n] = acc;
    }
}

// ---------------- host orchestration ----------------
template<typename T> static T* symaddr(const void* sym){
    void* p = nullptr; cudaGetSymbolAddress(&p, sym); return (T*)p;
}

extern "C" void kernel_launch(void* const* d_in, const int* in_sizes, int n_in,
                              void* d_out, int out_size)
{
    (void)in_sizes; (void)n_in; (void)out_size;
    const float* x      = (const float*)d_in[0];
    const float* eattr  = (const float*)d_in[1];
    const int*   eidx   = (const int*)  d_in[2];
    const float* esm    = (const float*)d_in[4];
    const float* Wq     = (const float*)d_in[5];
    const float* bq     = (const float*)d_in[6];
    const float* Wk     = (const float*)d_in[7];
    const float* bk     = (const float*)d_in[8];
    const float* Wv     = (const float*)d_in[9];
    const float* bv     = (const float*)d_in[10];
    const float* We     = (const float*)d_in[11];
    const float* Wskip  = (const float*)d_in[12];
    const float* bskip  = (const float*)d_in[13];
    const float* Wbeta  = (const float*)d_in[14];
    const float* Wt     = (const float*)d_in[15];
    const float* bt     = (const float*)d_in[16];
    const float* gamma  = (const float*)d_in[17];
    const float* betaBN = (const float*)d_in[18];
    const float* rmean  = (const float*)d_in[19];
    const float* rvar   = (const float*)d_in[20];
    const float* pw     = (const float*)d_in[21];
    const float* W1     = (const float*)d_in[22];
    const float* b1     = (const float*)d_in[23];
    const float* W2     = (const float*)d_in[24];
    const float* b2     = (const float*)d_in[25];
    const float* W3     = (const float*)d_in[26];
    const float* b3     = (const float*)d_in[27];

    const int* src = eidx;
    const int* dst = eidx + EC;

    float* q_    = symaddr<float>(g_q);
    float* k_    = symaddr<float>(g_k);
    float* v_    = symaddr<float>(g_v);
    float* xr_   = symaddr<float>(g_xr);
    float* h2_   = symaddr<float>(g_h2);
    float* P_    = symaddr<float>(g_P);
    float* T_    = symaddr<float>(g_T);
    float* hA_   = symaddr<float>(g_hA);
    float* hB_   = symaddr<float>(g_hB);
    int* deg_    = symaddr<int>(g_deg);
    int* row_    = symaddr<int>(g_row);
    int* csr_    = symaddr<int>(g_csr);
    int* nm_     = symaddr<int>(g_nmask);
    int* perm_   = symaddr<int>(g_perm);
    float* s_    = symaddr<float>(g_s);
    float* rep_  = symaddr<float>(g_rep);
    float* gin_  = symaddr<float>(g_gin);
    float* m1_   = symaddr<float>(g_m1);
    float* m2_   = symaddr<float>(g_m2);
    float* Wqe_  = symaddr<float>(g_Wqe);
    float* bPe_  = symaddr<float>(g_bPe);
    float* Wc_   = symaddr<float>(g_Wcomb);
    float* WbWe_ = symaddr<float>(g_WbWe);

    // precompute folded weights (deterministic; depends only on inputs)
    prec_wqe  <<<(5*128*512+255)/256, 256>>>(Wq, We, Wqe_);
    prec_bpe  <<<(5*128+255)/256, 256>>>(bq, We, bPe_);
    prec_wcomb<<<(5*576*128+255)/256, 256>>>(Wt, We, Wc_);

    const float* hin = x;
    float* bufs[2] = { hA_, hB_ };
    const int Mli[5] = { NNC, NNC, NNC/2, NNC/2, NNC/4 };

    for (int li=0; li<5; ++li){
        const float* WqL = Wq + (size_t)li*FD*HDC;
        const float* WkL = Wk + (size_t)li*FD*HDC;
        const float* WvL = Wv + (size_t)li*FD*HDC;
        const float* WsL = Wskip + (size_t)li*FD*HDC;
        const float* WbL = Wbeta + (size_t)li*3*HDC;
        int M = Mli[li];
        const int* pm = (li < 2) ? nullptr : perm_;

        gemm_qkvs<<<dim3(M/128, 17), 256>>>(hin, pm,
            WqL, WkL, WvL, WsL, Wqe_ + (size_t)li*128*512,
            bq + li*HDC, bk + li*HDC, bv + li*HDC, bskip + li*HDC, bPe_ + li*128,
            q_, k_, v_, xr_, P_);

        if (li == 0){
            prec_wbwe<<<(5*64+255)/256, 256>>>(We, Wbeta, WbWe_);
            k_init <<<NNC/256, 256>>>(deg_, nm_, 1);
            k_count<<<EC/256, 256>>>(src, dst, nm_, 0, deg_);
            k_scan <<<1, 256>>>(deg_, row_, deg_);
            k_fill <<<EC/256, 256>>>(src, dst, nm_, 0, deg_, csr_);
        }

        fused_attn<<<2048, 128>>>(q_, k_, v_, xr_, P_, eattr,
                                  WbL, WbWe_ + li*64,
                                  csr_, row_, src, pm, M, h2_, T_);

        float* hout = bufs[li & 1];
        gemm64<<<dim3(M/64, FD/64), 256>>>(h2_, T_, pm,
            Wc_ + (size_t)li*576*128, bt + li*FD, hout,
            gamma + li*FD, betaBN + li*FD, rmean + li*FD, rvar + li*FD);
        hin = hout;

        if (li == 1 || li == 3){
            int p = (li == 1) ? 0 : 1;
            int kkeep = (p == 0) ? NPG/2 : NPG/4;
            pool_score  <<<NNC/8, 256>>>(hout, pw + p*FD, s_);
            pool_rank   <<<BGR, 256>>>(s_, nm_, hout, kkeep, perm_);
            pool_readout<<<BGR, 128>>>(hout, nm_, rep_, p == 0);
            k_init <<<NNC/256, 256>>>(deg_, nm_, 0);
            k_count<<<EC/256, 256>>>(src, dst, nm_, 1, deg_);
            k_scan <<<1, 256>>>(deg_, row_, deg_);
            k_fill <<<EC/256, 256>>>(src, dst, nm_, 1, deg_, csr_);
        }
    }

    assemble_kernel<<<(BGR*1536)/256, 256>>>(rep_, esm, gin_);
    mlp_kernel<<<BGR, 256>>>(gin_, W1, b1, m1_, 1536, 512, 1);
    mlp_kernel<<<BGR, 256>>>(m1_,  W2, b2, m2_, 512, 256, 1);
    mlp_kernel<<<BGR, 32>>>(m2_,  W3, b3, (float*)d_out, 256, 10, 0);
}

// round 15
// speedup vs baseline: 1.2462x; 1.1863x over previous
#include <cuda_runtime.h>
#include <cuda_bf16.h>
#include <math.h>
#include <stdint.h>

// ---------------- problem constants ----------------
#define BGR   32
#define NPG   256
#define NNC   8192
#define EC    65536
#define FD    128
#define EDIMC 16
#define ESMC  1280
#define HC    4
#define DHC   128
#define HDC   512
#define ATTN_SCALE 0.08838834764831845f  // 1/sqrt(128)
#define CHUNK 64

// packed fp32 helpers (f32x2 pipe) — used by gemm64
#define FFMA2(d,a,b) asm("fma.rn.f32x2 %0, %1, %2, %0;" : "+l"(d) : "l"(a), "l"(b))
#define DUP2(d,s)    asm("mov.b64 %0, {%1, %1};" : "=l"(d) : "f"(s))

// warp-level bf16 MMA (sm_80+ baseline — no 'a' features)
#define MMA16816(c0,c1,c2,c3,a0,a1,a2,a3,b0,b1) \
    asm volatile("mma.sync.aligned.m16n8k16.row.col.f32.bf16.bf16.f32 " \
        "{%0,%1,%2,%3}, {%4,%5,%6,%7}, {%8,%9}, {%0,%1,%2,%3};" \
        : "+f"(c0),"+f"(c1),"+f"(c2),"+f"(c3) \
        : "r"(a0),"r"(a1),"r"(a2),"r"(a3),"r"(b0),"r"(b1))

// ---------------- device scratch ----------------
__device__ float g_q [NNC*HDC];
__device__ float g_k [NNC*HDC];
__device__ float g_v [NNC*HDC];
__device__ float g_xr[NNC*HDC];
__device__ float g_h2[NNC*HDC];
__device__ float g_P [NNC*64];
__device__ float g_T [NNC*64];
__device__ float g_hA[NNC*FD];
__device__ float g_hB[NNC*FD];
__device__ int   g_deg[NNC];
__device__ int   g_row[NNC+1];
__device__ int   g_csr[EC];
__device__ int   g_nmask[NNC];
__device__ int   g_perm[NNC];
__device__ float g_s[NNC];
__device__ float g_rep[BGR*256];
__device__ float g_gin[BGR*1536];
__device__ float g_m1[BGR*512];
__device__ float g_m2[BGR*256];
// precomputed weight folds (fp32)
__device__ float g_Wqe [5*128*512];
__device__ float g_bPe [5*128];
__device__ float g_Wcomb[5*576*128];
__device__ float g_WbWe [5*64];
// bf16 split buffers
__device__ __nv_bfloat16 g_Ahi[NNC*FD];
__device__ __nv_bfloat16 g_Alo[NNC*FD];
__device__ __nv_bfloat16 g_BWhi[5*5*512*128];   // [layer][seg][n=512][k=128]
__device__ __nv_bfloat16 g_BWlo[5*5*512*128];

// ---------------- precompute kernels (fp32 folds) ----------------
__global__ void prec_wqe(const float* __restrict__ Wq, const float* __restrict__ We,
                         float* __restrict__ Wqe)
{
    int idx = blockIdx.x*blockDim.x + threadIdx.x;
    if (idx >= 5*128*512) return;
    int li = idx / 65536;
    int r  = idx % 65536;
    int kk = r / 512, c = r % 512;
    float val = 0.f;
    if (c < 64){
        int h = c >> 4, j = c & 15;
        const float* a = Wq + (size_t)li*128*512 + (size_t)kk*512 + h*128;
        const float* b = We + (size_t)li*16*512 + (size_t)j*512 + h*128;
        for (int d=0; d<128; ++d) val += a[d]*b[d];
    }
    Wqe[idx] = val;
}
__global__ void prec_bpe(const float* __restrict__ bq, const float* __restrict__ We,
                         float* __restrict__ bPe)
{
    int idx = blockIdx.x*blockDim.x + threadIdx.x;
    if (idx >= 5*128) return;
    int li = idx / 128, c = idx % 128;
    float val = 0.f;
    if (c < 64){
        int h = c >> 4, j = c & 15;
        const float* a = bq + (size_t)li*512 + h*128;
        const float* b = We + (size_t)li*16*512 + (size_t)j*512 + h*128;
        for (int d=0; d<128; ++d) val += a[d]*b[d];
    }
    bPe[idx] = val;
}
__global__ void prec_wcomb(const float* __restrict__ Wt, const float* __restrict__ We,
                           float* __restrict__ Wc)
{
    int idx = blockIdx.x*blockDim.x + threadIdx.x;
    if (idx >= 5*576*128) return;
    int li = idx / (576*128);
    int r  = idx % (576*128);
    int rowk = r / 128, f = r % 128;
    float val;
    if (rowk < 512){
        val = Wt[(size_t)li*512*128 + (size_t)rowk*128 + f];
    } else {
        int c = rowk - 512;
        int h = c >> 4, j = c & 15;
        const float* we = We + (size_t)li*16*512 + (size_t)j*512 + h*128;
        const float* wt = Wt + (size_t)li*512*128 + (size_t)(h*128)*128 + f;
        float s = 0.f;
        for (int d=0; d<128; ++d) s += we[d]*wt[(size_t)d*128];
        val = s;
    }
    Wc[idx] = val;
}
__global__ void prec_wbwe(const float* __restrict__ We, const float* __restrict__ Wbeta,
                          float* __restrict__ WbWe)
{
    int idx = blockIdx.x*blockDim.x + threadIdx.x;
    if (idx >= 5*64) return;
    int li = idx / 64, c = idx % 64;
    int h = c >> 4, j = c & 15;
    const float* we = We + (size_t)li*16*512 + (size_t)j*512 + h*128;
    const float* w1 = Wbeta + (size_t)li*1536 + h*128;
    const float* w3 = Wbeta + (size_t)li*1536 + 1024 + h*128;
    float s = 0.f;
    for (int d=0; d<128; ++d) s += we[d]*(w1[d]+w3[d]);
    WbWe[idx] = s;
}

// ---------------- bf16 split conversions ----------------
__global__ void conv_split(const float* __restrict__ X,
                           __nv_bfloat16* __restrict__ hi, __nv_bfloat16* __restrict__ lo, int n)
{
    int i = blockIdx.x*blockDim.x + threadIdx.x;
    if (i < n){
        float x = X[i];
        __nv_bfloat16 h = __float2bfloat16(x);
        hi[i] = h;
        lo[i] = __float2bfloat16(x - __bfloat162float(h));
    }
}
// BW[li][seg][n][k] = W_seg[li][k][n] split into hi/lo. seg4 from Wqe (cols<64; rest 0).
__global__ void conv_W(const float* __restrict__ Wq, const float* __restrict__ Wk,
                       const float* __restrict__ Wv, const float* __restrict__ Ws,
                       const float* __restrict__ Wqe,
                       __nv_bfloat16* __restrict__ bwhi, __nv_bfloat16* __restrict__ bwlo)
{
    int idx = blockIdx.x*blockDim.x + threadIdx.x;
    if (idx >= 5*5*512*128) return;
    int li  = idx / (5*512*128);
    int r   = idx % (5*512*128);
    int seg = r / (512*128);
    int r2  = r % (512*128);
    int n   = r2 / 128, kk = r2 % 128;
    float x = 0.f;
    if (seg == 0)      x = Wq [(size_t)li*65536 + (size_t)kk*512 + n];
    else if (seg == 1) x = Wk [(size_t)li*65536 + (size_t)kk*512 + n];
    else if (seg == 2) x = Wv [(size_t)li*65536 + (size_t)kk*512 + n];
    else if (seg == 3) x = Ws [(size_t)li*65536 + (size_t)kk*512 + n];
    else if (n < 64)   x = Wqe[(size_t)li*65536 + (size_t)kk*512 + n];
    __nv_bfloat16 h = __float2bfloat16(x);
    bwhi[idx] = h;
    bwlo[idx] = __float2bfloat16(x - __bfloat162float(h));
}

// ---------------- CSR build ----------------
__global__ void k_init(int* deg, int* nmask, int initMask){
    int i = blockIdx.x*blockDim.x + threadIdx.x;
    if (i < NNC){ deg[i]=0; if (initMask) nmask[i]=1; }
}
__global__ void k_count(const int* __restrict__ src, const int* __restrict__ dst,
                        const int* __restrict__ nmask, int useMask, int* deg){
    int e = blockIdx.x*blockDim.x + threadIdx.x;
    if (e < EC){
        int d = dst[e];
        if (!useMask || (nmask[d] && nmask[src[e]])) atomicAdd(&deg[d], 1);
    }
}
__global__ void k_scan(int* deg, int* row, int* cur){
    __shared__ int part[256];
    int t = threadIdx.x;
    int base = t*32;
    int loc[32];
    int s = 0;
    for (int i=0;i<32;i++){ loc[i] = deg[base+i]; s += loc[i]; }
    part[t] = s;
    __syncthreads();
    if (t == 0){
        int run = 0;
        for (int i=0;i<256;i++){ int tmp = part[i]; part[i] = run; run += tmp; }
    }
    __syncthreads();
    int run = part[t];
    for (int i=0;i<32;i++){ row[base+i] = run; cur[base+i] = run; run += loc[i]; }
    if (t == 255) row[NNC] = run;
}
__global__ void k_fill(const int* __restrict__ src, const int* __restrict__ dst,
                       const int* __restrict__ nmask, int useMask,
                       int* cur, int* csr){
    int e = blockIdx.x*blockDim.x + threadIdx.x;
    if (e < EC){
        int d = dst[e];
        if (!useMask || (nmask[d] && nmask[src[e]])){
            int pos = atomicAdd(&cur[d], 1);
            csr[pos] = e;
        }
    }
}

// ---------------- HMMA split-bf16 GEMM: q/k/v/skip/P ----------------
// Block tile 128(M) x 128(N), K=128 in chunks of 32. 8 warps (2x4), warp tile 64x32.
// smem rows padded to 40 bf16 (80B) -> conflict-free direct b32 fragment loads.
#define PAD 40
__global__ void __launch_bounds__(256) gemm_mma(
    const __nv_bfloat16* __restrict__ Ahi, const __nv_bfloat16* __restrict__ Alo,
    const __nv_bfloat16* __restrict__ BWhi, const __nv_bfloat16* __restrict__ BWlo,
    const int* __restrict__ perm, int li,
    const float* __restrict__ b0, const float* __restrict__ b1,
    const float* __restrict__ b2, const float* __restrict__ b3,
    const float* __restrict__ bP,
    float* __restrict__ C0, float* __restrict__ C1,
    float* __restrict__ C2, float* __restrict__ C3,
    float* __restrict__ CP)
{
    __shared__ __nv_bfloat16 Asm[2][128*PAD];   // [hi|lo]
    __shared__ __nv_bfloat16 Bsm[2][128*PAD];
    int tid = threadIdx.x;
    int lane = tid & 31, warp = tid >> 5;
    int g = lane >> 2, tig = lane & 3;
    int wm = warp >> 2, wn = warp & 3;          // warp grid 2x4
    int y = blockIdx.y;
    int seg = (y >= 16) ? 4 : (y >> 2);
    int n0  = (y >= 16) ? 0 : ((y & 3) << 7);
    int m0  = blockIdx.x << 7;

    const __nv_bfloat16* BWhiL = BWhi + ((size_t)li*5 + seg)*512*128 + (size_t)n0*128;
    const __nv_bfloat16* BWloL = BWlo + ((size_t)li*5 + seg)*512*128 + (size_t)n0*128;

    float acc[4][4][4];
#pragma unroll
    for (int i=0;i<4;i++)
#pragma unroll
        for (int j=0;j<4;j++)
#pragma unroll
            for (int r=0;r<4;r++) acc[i][j][r] = 0.f;

    for (int ch = 0; ch < 4; ++ch){
        // stage A (128 rows x 32 bf16, hi+lo) and B likewise
        for (int i = tid; i < 128*4; i += 256){
            int r = i >> 2, u = i & 3;
            int node = perm ? perm[m0 + r] : (m0 + r);
            *(uint4*)&Asm[0][r*PAD + u*8] = *(const uint4*)(Ahi + (size_t)node*128 + ch*32 + u*8);
            *(uint4*)&Asm[1][r*PAD + u*8] = *(const uint4*)(Alo + (size_t)node*128 + ch*32 + u*8);
        }
        for (int i = tid; i < 128*4; i += 256){
            int r = i >> 2, u = i & 3;
            *(uint4*)&Bsm[0][r*PAD + u*8] = *(const uint4*)(BWhiL + (size_t)r*128 + ch*32 + u*8);
            *(uint4*)&Bsm[1][r*PAD + u*8] = *(const uint4*)(BWloL + (size_t)r*128 + ch*32 + u*8);
        }
        __syncthreads();

#pragma unroll
        for (int pass = 0; pass < 3; ++pass){
            int as = (pass == 2) ? 1 : 0;      // (hi,hi),(hi,lo),(lo,hi)
            int bs = (pass == 1) ? 1 : 0;
#pragma unroll
            for (int ks = 0; ks < 2; ++ks){
                int col = ks*16 + tig*2;
                uint32_t bf[4][2];
#pragma unroll
                for (int j=0;j<4;j++){
                    int brow = wn*32 + j*8 + g;
                    bf[j][0] = *(const uint32_t*)&Bsm[bs][brow*PAD + col];
                    bf[j][1] = *(const uint32_t*)&Bsm[bs][brow*PAD + col + 8];
                }
#pragma unroll
                for (int i=0;i<4;i++){
                    int arow = wm*64 + i*16 + g;
                    uint32_t a0 = *(const uint32_t*)&Asm[as][arow*PAD + col];
                    uint32_t a1 = *(const uint32_t*)&Asm[as][(arow+8)*PAD + col];
                    uint32_t a2 = *(const uint32_t*)&Asm[as][arow*PAD + col + 8];
                    uint32_t a3 = *(const uint32_t*)&Asm[as][(arow+8)*PAD + col + 8];
#pragma unroll
                    for (int j=0;j<4;j++){
                        MMA16816(acc[i][j][0], acc[i][j][1], acc[i][j][2], acc[i][j][3],
                                 a0, a1, a2, a3, bf[j][0], bf[j][1]);
                    }
                }
            }
        }
        __syncthreads();
    }

    // ---- epilogue ----
    if (seg < 4){
        float* C = seg==0?C0: seg==1?C1: seg==2?C2:C3;
        const float* bias = seg==0?b0: seg==1?b1: seg==2?b2:b3;
#pragma unroll
        for (int i=0;i<4;i++){
            int mA = m0 + wm*64 + i*16 + g;
            int mB = mA + 8;
            int nodeA = perm ? perm[mA] : mA;
            int nodeB = perm ? perm[mB] : mB;
#pragma unroll
            for (int j=0;j<4;j++){
                int n = n0 + wn*32 + j*8 + tig*2;
                float bi0 = bias[n], bi1 = bias[n+1];
                float* ca = C + (size_t)nodeA*HDC + n;
                float* cb = C + (size_t)nodeB*HDC + n;
                ca[0] = acc[i][j][0] + bi0; ca[1] = acc[i][j][1] + bi1;
                cb[0] = acc[i][j][2] + bi0; cb[1] = acc[i][j][3] + bi1;
            }
        }
    } else {
#pragma unroll
        for (int i=0;i<4;i++){
            int mA = m0 + wm*64 + i*16 + g;
            int mB = mA + 8;
            int nodeA = perm ? perm[mA] : mA;
            int nodeB = perm ? perm[mB] : mB;
#pragma unroll
            for (int j=0;j<4;j++){
                int n = wn*32 + j*8 + tig*2;
                if (n < 64){
                    float bi0 = bP[n], bi1 = bP[n+1];
                    float* ca = CP + (size_t)nodeA*64 + n;
                    float* cb = CP + (size_t)nodeB*64 + n;
                    ca[0] = acc[i][j][0] + bi0; ca[1] = acc[i][j][1] + bi1;
                    cb[0] = acc[i][j][2] + bi0; cb[1] = acc[i][j][3] + bi1;
                }
            }
        }
    }
}

// ---------------- GEMM 64x64, K=576 (h2core | T), ReLU+BN epilogue, f32x2 ----------------
__global__ void __launch_bounds__(256) gemm64(
    const float* __restrict__ h2, const float* __restrict__ T,
    const int* __restrict__ perm,
    const float* __restrict__ Wc, const float* __restrict__ bias,
    float* __restrict__ C,
    const float* __restrict__ gamma, const float* __restrict__ beta,
    const float* __restrict__ rmean, const float* __restrict__ rvar)
{
    const int N = 128, K = 576;
    __shared__ float As[16][64];
    __shared__ float Bs[16][64];
    int m0 = blockIdx.x*64, n0 = blockIdx.y*64;
    int tid = threadIdx.x;
    int ty = tid >> 4, tx = tid & 15;
    unsigned long long acc[4][2];
#pragma unroll
    for (int i=0;i<4;i++){ acc[i][0]=0ull; acc[i][1]=0ull; }
    int ar = tid >> 2, ac = (tid & 3) << 2;
    int wr = tid >> 4, wc = (tid & 15) << 2;
    int nodeA = perm ? perm[m0 + ar] : (m0 + ar);
    const float* Ah = h2 + (size_t)nodeA*512 + ac;
    const float* At = T  + (size_t)nodeA*64 + ac;
    const float* Wptr = Wc + (size_t)wr*N + n0+wc;

    float4 av = *(const float4*)(Ah);
    float4 wv = *(const float4*)(Wptr);

    for (int k0=0; k0<K; k0+=16){
        As[ac+0][ar]=av.x; As[ac+1][ar]=av.y; As[ac+2][ar]=av.z; As[ac+3][ar]=av.w;
        *(float4*)&Bs[wr][wc] = wv;
        __syncthreads();
        int k1 = k0 + 16;
        if (k1 < K){
            av = (k1 < 512) ? *(const float4*)(Ah + k1)
                            : *(const float4*)(At + (k1-512));
            wv = *(const float4*)(Wptr + (size_t)k1*N);
        }
#pragma unroll
        for (int kk=0; kk<16; ++kk){
            float4 ra = *(const float4*)&As[kk][ty*4];
            ulonglong2 rb = *(const ulonglong2*)&Bs[kk][tx*4];
            unsigned long long rp[4];
            DUP2(rp[0], ra.x); DUP2(rp[1], ra.y); DUP2(rp[2], ra.z); DUP2(rp[3], ra.w);
#pragma unroll
            for (int i=0;i<4;i++){
                FFMA2(acc[i][0], rp[i], rb.x);
                FFMA2(acc[i][1], rp[i], rb.y);
            }
        }
        __syncthreads();
    }
#pragma unroll
    for (int i=0;i<4;i++){
        int nodeC = perm ? perm[m0+ty*4+i] : (m0+ty*4+i);
#pragma unroll
        for (int j=0;j<4;j++){
            int n = n0 + tx*4 + j;
            float2 p = *(float2*)&acc[i][j>>1];
            float c = ((j&1) ? p.y : p.x) + bias[n];
            c = fmaxf(c, 0.f);
            c = (c - rmean[n]) * rsqrtf(rvar[n] + 1e-5f) * gamma[n] + beta[n];
            C[(size_t)nodeC*N + n] = c;
        }
    }
}

// ---------------- fused attention (outputs h2core + T) ----------------
__global__ void __launch_bounds__(128) fused_attn(
    const float* __restrict__ q, const float* __restrict__ k,
    const float* __restrict__ v, const float* __restrict__ xr,
    const float* __restrict__ P, const float* __restrict__ eattr,
    const float* __restrict__ Wb, const float* __restrict__ WbWeL,
    const int* __restrict__ csr, const int* __restrict__ row,
    const int* __restrict__ src, const int* __restrict__ perm, int nlive,
    float* __restrict__ h2, float* __restrict__ Tout)
{
    __shared__ float sS[4][CHUNK];
    __shared__ float red[4];
    __shared__ float btaSh;
    int tid  = threadIdx.x;
    int warp = tid >> 5, lane = tid & 31;
    int off  = warp*128 + lane*4;
    float wbwe_reg = (lane < 16) ? WbWeL[warp*16 + lane] : 0.f;

    for (int ni = blockIdx.x; ni < nlive; ni += gridDim.x){
        int n = perm ? perm[ni] : ni;
        __syncthreads();
        int r0 = row[n], r1 = row[n+1];
        float4 qf = *(const float4*)(q + (size_t)n*HDC + off);
        float Pj = (lane < 16) ? P[(size_t)n*64 + warp*16 + lane] : 0.f;

        float m = -1e30f, den = 0.f;
        float a0=0.f,a1=0.f,a2=0.f,a3=0.f;
        float Te = 0.f;

        for (int c0 = r0; c0 < r1; c0 += CHUNK){
            int cnt = min(CHUNK, r1 - c0);
            int i = 0;
            for (; i+1 < cnt; i += 2){
                int ea_ = csr[c0+i], eb_ = csr[c0+i+1];
                int sa_ = src[ea_],  sb_ = src[eb_];
                float4 ka = *(const float4*)(k + (size_t)sa_*HDC + off);
                float4 kb = *(const float4*)(k + (size_t)sb_*HDC + off);
                float eaa = (lane < 16) ? eattr[(size_t)ea_*EDIMC + lane] : 0.f;
                float eab = (lane < 16) ? eattr[(size_t)eb_*EDIMC + lane] : 0.f;
                float pa = qf.x*ka.x + qf.y*ka.y + qf.z*ka.z + qf.w*ka.w + Pj*eaa;
                float pb = qf.x*kb.x + qf.y*kb.y + qf.z*kb.z + qf.w*kb.w + Pj*eab;
#pragma unroll
                for (int o=16;o;o>>=1){
                    pa += __shfl_xor_sync(0xffffffffu, pa, o);
                    pb += __shfl_xor_sync(0xffffffffu, pb, o);
                }
                if (lane == 0){
                    sS[warp][i]   = pa * ATTN_SCALE;
                    sS[warp][i+1] = pb * ATTN_SCALE;
                }
            }
            if (i < cnt){
                int ea_ = csr[c0+i];
                int sa_ = src[ea_];
                float4 ka = *(const float4*)(k + (size_t)sa_*HDC + off);
                float eaa = (lane < 16) ? eattr[(size_t)ea_*EDIMC + lane] : 0.f;
                float pa = qf.x*ka.x + qf.y*ka.y + qf.z*ka.z + qf.w*ka.w + Pj*eaa;
#pragma unroll
                for (int o=16;o;o>>=1) pa += __shfl_xor_sync(0xffffffffu, pa, o);
                if (lane == 0) sS[warp][i] = pa * ATTN_SCALE;
            }
            __syncwarp();
            float v0 = (lane      < cnt) ? sS[warp][lane]      : -1e30f;
            float v1 = (lane+32   < cnt) ? sS[warp][lane+32]   : -1e30f;
            float cm = fmaxf(v0, v1);
#pragma unroll
            for (int o=16;o;o>>=1) cm = fmaxf(cm, __shfl_xor_sync(0xffffffffu, cm, o));
            float mN = fmaxf(m, cm);
            float corr = expf(m - mN);
            den *= corr; a0 *= corr; a1 *= corr; a2 *= corr; a3 *= corr; Te *= corr;
            m = mN;
            float w0 = (lane    < cnt) ? expf(v0 - mN) : 0.f;
            float w1 = (lane+32 < cnt) ? expf(v1 - mN) : 0.f;
            if (lane      < cnt) sS[warp][lane]    = w0;
            if (lane+32   < cnt) sS[warp][lane+32] = w1;
            float ds = w0 + w1;
#pragma unroll
            for (int o=16;o;o>>=1) ds += __shfl_xor_sync(0xffffffffu, ds, o);
            den += ds;
            __syncwarp();
            for (int j=0; j<cnt; ++j){
                int e = csr[c0+j];
                int s = src[e];
                float w = sS[warp][j];
                float4 vf = *(const float4*)(v + (size_t)s*HDC + off);
                a0 += w*vf.x; a1 += w*vf.y; a2 += w*vf.z; a3 += w*vf.w;
                if (lane < 16) Te += w * eattr[(size_t)e*EDIMC + lane];
            }
            __syncwarp();
        }
        float inv = 1.f/fmaxf(den, 1e-16f);
        float tp  = (lane < 16) ? Te * inv : 0.f;
        float o0=a0*inv, o1=a1*inv, o2=a2*inv, o3=a3*inv;

        float4 xrf = *(const float4*)(xr + (size_t)n*HDC + off);
        const float* WbA = Wb + off;
        const float* WbB = Wb + HDC + off;
        const float* WbC = Wb + 2*HDC + off;
        float part = o0*WbA[0] + o1*WbA[1] + o2*WbA[2] + o3*WbA[3]
                   + xrf.x*WbB[0] + xrf.y*WbB[1] + xrf.z*WbB[2] + xrf.w*WbB[3]
                   + (o0-xrf.x)*WbC[0] + (o1-xrf.y)*WbC[1]
                   + (o2-xrf.z)*WbC[2] + (o3-xrf.w)*WbC[3]
                   + wbwe_reg * tp;
#pragma unroll
        for (int o=16;o;o>>=1) part += __shfl_xor_sync(0xffffffffu, part, o);
        if (lane == 0) red[warp] = part;
        __syncthreads();
        if (tid == 0) btaSh = 1.f/(1.f + expf(-(red[0]+red[1]+red[2]+red[3])));
        __syncthreads();
        float bta = btaSh;
        float* hr = h2 + (size_t)n*HDC + off;
        hr[0] = bta*xrf.x + (1.f-bta)*o0;
        hr[1] = bta*xrf.y + (1.f-bta)*o1;
        hr[2] = bta*xrf.z + (1.f-bta)*o2;
        hr[3] = bta*xrf.w + (1.f-bta)*o3;
        if (lane < 16) Tout[(size_t)n*64 + warp*16 + lane] = (1.f-bta)*tp;
    }
}

// ---------------- pooling ----------------
__global__ void pool_score(const float* __restrict__ h, const float* __restrict__ w,
                           float* __restrict__ sArr)
{
    int gw = (blockIdx.x*blockDim.x + threadIdx.x) >> 5;
    int lane = threadIdx.x & 31;
    if (gw >= NNC) return;
    const float* hr = h + (size_t)gw*FD;
    float4 hv = *(const float4*)&hr[lane*4];
    float4 wv = *(const float4*)&w[lane*4];
    float dot = hv.x*wv.x + hv.y*wv.y + hv.z*wv.z + hv.w*wv.w;
    float nw  = wv.x*wv.x + wv.y*wv.y + wv.z*wv.z + wv.w*wv.w;
#pragma unroll
    for (int off=16; off; off>>=1){
        dot += __shfl_xor_sync(0xffffffffu, dot, off);
        nw  += __shfl_xor_sync(0xffffffffu, nw , off);
    }
    if (lane == 0) sArr[gw] = tanhf(dot / sqrtf(nw));
}

__global__ void pool_rank(const float* __restrict__ sArr, int* __restrict__ nmask,
                          float* __restrict__ h, int kkeep, int* __restrict__ perm)
{
    __shared__ float ss[256];
    __shared__ float scl[256];
    __shared__ int   kp[256];
    int b = blockIdx.x, t = threadIdx.x;
    int n = b*NPG + t;
    int m0 = nmask[n];
    float sv = sArr[n];
    ss[t] = m0 ? sv : -INFINITY;
    __syncthreads();
    float mys = ss[t];
    int rank = 0;
    for (int j=0; j<NPG; ++j){
        float o = ss[j];
        rank += (o > mys) || (o == mys && j < t);
    }
    int keep = (rank < kkeep) && m0;
    nmask[n] = keep;
    scl[t] = keep ? sv : 0.f;
    kp[t]  = keep;
    __syncthreads();
    if (keep){
        int pos = 0;
        for (int j=0; j<t; ++j) pos += kp[j];
        perm[b*kkeep + pos] = n;
    }
    for (int idx=t; idx<NPG*FD; idx+=256){
        int ln = idx >> 7, f = idx & 127;
        h[(size_t)(b*NPG+ln)*FD + f] *= scl[ln];
    }
}

__global__ void pool_readout(const float* __restrict__ h, const int* __restrict__ nmask,
                             float* __restrict__ rep, int first)
{
    int b = blockIdx.x, f = threadIdx.x;
    float mx = -1e30f, sm = 0.f, cnt = 0.f;
    for (int j=0; j<NPG; ++j){
        int n = b*NPG + j;
        int kp = nmask[n];
        float hv = h[(size_t)n*FD + f];
        mx = fmaxf(mx, kp ? hv : -1e30f);
        sm += hv;
        cnt += kp ? 1.f : 0.f;
    }
    float gmean = sm / fmaxf(cnt, 1.f);
    int o = b*256 + f;
    if (first){ rep[o] = mx; rep[o+128] = gmean; }
    else      { rep[o] += mx; rep[o+128] += gmean; }
}

// ---------------- head MLP ----------------
__global__ void assemble_kernel(const float* __restrict__ rep, const float* __restrict__ esm,
                                float* __restrict__ gin)
{
    int idx = blockIdx.x*blockDim.x + threadIdx.x;
    if (idx >= BGR*1536) return;
    int b = idx / 1536, c = idx % 1536;
    gin[idx] = (c < 256) ? rep[b*256 + c] : esm[(size_t)b*ESMC + (c-256)];
}

__global__ void mlp_kernel(const float* __restrict__ A, const float* __restrict__ W,
                           const float* __restrict__ bias, float* __restrict__ C,
                           int Kd, int Nd, int doRelu)
{
    int b = blockIdx.x;
    for (int n = threadIdx.x; n < Nd; n += blockDim.x){
        float acc = 0.f;
        for (int k=0; k<Kd; ++k) acc += A[(size_t)b*Kd + k] * W[(size_t)k*Nd + n];
        acc += bias[n];
        if (doRelu) acc = fmaxf(acc, 0.f);
        C[(size_t)b*Nd + n] = acc;
    }
}

// ---------------- host orchestration ----------------
template<typename T> static T* symaddr(const void* sym){
    void* p = nullptr; cudaGetSymbolAddress(&p, sym); return (T*)p;
}

extern "C" void kernel_launch(void* const* d_in, const int* in_sizes, int n_in,
                              void* d_out, int out_size)
{
    (void)in_sizes; (void)n_in; (void)out_size;
    const float* x      = (const float*)d_in[0];
    const float* eattr  = (const float*)d_in[1];
    const int*   eidx   = (const int*)  d_in[2];
    const float* esm    = (const float*)d_in[4];
    const float* Wq     = (const float*)d_in[5];
    const float* bq     = (const float*)d_in[6];
    const float* Wk     = (const float*)d_in[7];
    const float* bk     = (const float*)d_in[8];
    const float* Wv     = (const float*)d_in[9];
    const float* bv     = (const float*)d_in[10];
    const float* We     = (const float*)d_in[11];
    const float* Wskip  = (const float*)d_in[12];
    const float* bskip  = (const float*)d_in[13];
    const float* Wbeta  = (const float*)d_in[14];
    const float* Wt     = (const float*)d_in[15];
    const float* bt     = (const float*)d_in[16];
    const float* gamma  = (const float*)d_in[17];
    const float* betaBN = (const float*)d_in[18];
    const float* rmean  = (const float*)d_in[19];
    const float* rvar   = (const float*)d_in[20];
    const float* pw     = (const float*)d_in[21];
    const float* W1     = (const float*)d_in[22];
    const float* b1     = (const float*)d_in[23];
    const float* W2     = (const float*)d_in[24];
    const float* b2     = (const float*)d_in[25];
    const float* W3     = (const float*)d_in[26];
    const float* b3     = (const float*)d_in[27];

    const int* src = eidx;
    const int* dst = eidx + EC;

    float* q_    = symaddr<float>(g_q);
    float* k_    = symaddr<float>(g_k);
    float* v_    = symaddr<float>(g_v);
    float* xr_   = symaddr<float>(g_xr);
    float* h2_   = symaddr<float>(g_h2);
    float* P_    = symaddr<float>(g_P);
    float* T_    = symaddr<float>(g_T);
    float* hA_   = symaddr<float>(g_hA);
    float* hB_   = symaddr<float>(g_hB);
    int* deg_    = symaddr<int>(g_deg);
    int* row_    = symaddr<int>(g_row);
    int* csr_    = symaddr<int>(g_csr);
    int* nm_     = symaddr<int>(g_nmask);
    int* perm_   = symaddr<int>(g_perm);
    float* s_    = symaddr<float>(g_s);
    float* rep_  = symaddr<float>(g_rep);
    float* gin_  = symaddr<float>(g_gin);
    float* m1_   = symaddr<float>(g_m1);
    float* m2_   = symaddr<float>(g_m2);
    float* Wqe_  = symaddr<float>(g_Wqe);
    float* bPe_  = symaddr<float>(g_bPe);
    float* Wc_   = symaddr<float>(g_Wcomb);
    float* WbWe_ = symaddr<float>(g_WbWe);
    __nv_bfloat16* Ahi_  = symaddr<__nv_bfloat16>(g_Ahi);
    __nv_bfloat16* Alo_  = symaddr<__nv_bfloat16>(g_Alo);
    __nv_bfloat16* BWhi_ = symaddr<__nv_bfloat16>(g_BWhi);
    __nv_bfloat16* BWlo_ = symaddr<__nv_bfloat16>(g_BWlo);

    // precompute folds + bf16 weight conversion (deterministic per call)
    prec_wqe  <<<(5*128*512+255)/256, 256>>>(Wq, We, Wqe_);
    conv_W    <<<(5*5*512*128+255)/256, 256>>>(Wq, Wk, Wv, Wskip, Wqe_, BWhi_, BWlo_);
    prec_bpe  <<<(5*128+255)/256, 256>>>(bq, We, bPe_);
    prec_wcomb<<<(5*576*128+255)/256, 256>>>(Wt, We, Wc_);
    prec_wbwe <<<(5*64+255)/256, 256>>>(We, Wbeta, WbWe_);

    const float* hin = x;
    float* bufs[2] = { hA_, hB_ };
    const int Mli[5] = { NNC, NNC, NNC/2, NNC/2, NNC/4 };

    for (int li=0; li<5; ++li){
        const float* WbL = Wbeta + (size_t)li*3*HDC;
        int M = Mli[li];
        const int* pm = (li < 2) ? nullptr : perm_;

        conv_split<<<(NNC*FD)/256, 256>>>(hin, Ahi_, Alo_, NNC*FD);

        gemm_mma<<<dim3(M/128, 17), 256>>>(
            Ahi_, Alo_, BWhi_, BWlo_, pm, li,
            bq + li*HDC, bk + li*HDC, bv + li*HDC, bskip + li*HDC, bPe_ + li*128,
            q_, k_, v_, xr_, P_);

        if (li == 0){
            k_init <<<NNC/256, 256>>>(deg_, nm_, 1);
            k_count<<<EC/256, 256>>>(src, dst, nm_, 0, deg_);
            k_scan <<<1, 256>>>(deg_, row_, deg_);
            k_fill <<<EC/256, 256>>>(src, dst, nm_, 0, deg_, csr_);
        }

        fused_attn<<<2048, 128>>>(q_, k_, v_, xr_, P_, eattr,
                                  WbL, WbWe_ + li*64,
                                  csr_, row_, src, pm, M, h2_, T_);

        float* hout = bufs[li & 1];
        gemm64<<<dim3(M/64, FD/64), 256>>>(h2_, T_, pm,
            Wc_ + (size_t)li*576*128, bt + li*FD, hout,
            gamma + li*FD, betaBN + li*FD, rmean + li*FD, rvar + li*FD);
        hin = hout;

        if (li == 1 || li == 3){
            int p = (li == 1) ? 0 : 1;
            int kkeep = (p == 0) ? NPG/2 : NPG/4;
            pool_score  <<<NNC/8, 256>>>(hout, pw + p*FD, s_);
            pool_rank   <<<BGR, 256>>>(s_, nm_, hout, kkeep, perm_);
            pool_readout<<<BGR, 128>>>(hout, nm_, rep_, p == 0);
            k_init <<<NNC/256, 256>>>(deg_, nm_, 0);
            k_count<<<EC/256, 256>>>(src, dst, nm_, 1, deg_);
            k_scan <<<1, 256>>>(deg_, row_, deg_);
            k_fill <<<EC/256, 256>>>(src, dst, nm_, 1, deg_, csr_);
        }
    }

    assemble_kernel<<<(BGR*1536)/256, 256>>>(rep_, esm, gin_);
    mlp_kernel<<<BGR, 256>>>(gin_, W1, b1, m1_, 1536, 512, 1);
    mlp_kernel<<<BGR, 256>>>(m1_,  W2, b2, m2_, 512, 256, 1);
    mlp_kernel<<<BGR, 32>>>(m2_,  W3, b3, (float*)d_out, 256, 10, 0);
}